// round 7
// baseline (speedup 1.0000x reference)
#include <cuda_runtime.h>

namespace {
constexpr int Hn = 1024;   // time steps

__device__ __forceinline__ float tanh_fast(float x){ float r; asm("tanh.approx.f32 %0, %1;" : "=f"(r) : "f"(x)); return r; }
__device__ __forceinline__ float ex2_fast (float x){ float r; asm("ex2.approx.ftz.f32 %0, %1;" : "=f"(r) : "f"(x)); return r; }
__device__ __forceinline__ float lg2_fast (float x){ float r; asm("lg2.approx.ftz.f32 %0, %1;" : "=f"(r) : "f"(x)); return r; }
__device__ __forceinline__ float rcp_fast (float x){ float r; asm("rcp.approx.ftz.f32 %0, %1;" : "=f"(r) : "f"(x)); return r; }
// softplus given pre-scaled (log2e) argument: log2(1 + 2^y)
__device__ __forceinline__ float sp_pre(float y){ return lg2_fast(1.0f + ex2_fast(y)); }
__device__ __forceinline__ float shflx(float v, int m){ return __shfl_xor_sync(0xffffffffu, v, m); }
__device__ __forceinline__ float shfli(float v, int s){ return __shfl_sync(0xffffffffu, v, s); }
}

// 2 batteries/warp, 16 lanes/battery (every warp-instruction serves both
// batteries). Uniform 2 warps per SMSP: the sibling warp fills all chain-stall
// bubbles (R1 evidence: 87% issue). Issue count per warp-step minimized:
// packed 4-quantity butterfly for R0/R1/C1/resid (19 issues vs 48),
// per-lane softplus, plain 4-stage butterfly for Q.
__global__ void __launch_bounds__(256, 1) dci_rollout(
    const float* __restrict__ gI, const float* __restrict__ gT, const float* __restrict__ soc0,
    const float* __restrict__ W1p, const float* __restrict__ b1p,
    const float* __restrict__ W2p, const float* __restrict__ b2p,
    const float* __restrict__ W1r, const float* __restrict__ b1r,
    const float* __restrict__ W2r, const float* __restrict__ b2r,
    float* __restrict__ out)
{
    const int lane = threadIdx.x & 31;
    const int g    = lane & 15;
    const int base = lane & 16;      // battery's lane-group base within warp
    const int bat  = ((blockIdx.x * blockDim.x + threadIdx.x) >> 5) * 2 + (lane >> 4);

    constexpr float LOG2E = 1.4426950408889634f;
    constexpr float LN2   = 0.6931471805599453f;
    constexpr float EPS   = 1e-6f;

    // --- weights into registers; W2 columns pre-scaled by log2e ---
    float w0[8], w1[8], w2[8], wb[8];
    float wx[8], wy[8], wz[8], wq[8];
#pragma unroll
    for (int k = 0; k < 8; ++k) {
        int u = g + 16 * k;
        w0[k] = W1p[u]; w1[k] = W1p[128 + u]; w2[k] = W1p[256 + u]; wb[k] = b1p[u];
        float4 wp = reinterpret_cast<const float4*>(W2p)[u];   // [R0,R1,C1,Q] row u
        wx[k] = wp.x * LOG2E; wy[k] = wp.y * LOG2E; wz[k] = wp.z * LOG2E; wq[k] = wp.w * LOG2E;
    }
    float q0[4], q1[4], q2[4], qb[4], qw[4];
#pragma unroll
    for (int k = 0; k < 4; ++k) {
        int u = g + 16 * k;
        q0[k] = W1r[u]; q1[k] = W1r[64 + u]; q2[k] = W1r[128 + u]; qb[k] = b1r[u];
        qw[k] = W2r[u];
    }
    float4 b2 = *reinterpret_cast<const float4*>(b2p);
    // biases pre-scaled (log2e for softplus args), divided by 16 per lane
    const float bx16 = b2.x * (LOG2E / 16.0f);
    const float by16 = b2.y * (LOG2E / 16.0f);
    const float bz16 = b2.z * (LOG2E / 16.0f);
    const float bq16 = b2.w * (LOG2E / 16.0f);
    const float br16 = b2r[0] * (1.0f / 16.0f);

    // packed-reduce lane role: quantity = g&3 (0:R0, 1:R1, 2:C1, 3:resid)
    const int   qq    = g & 3;
    const float sclq  = (qq == 0) ? 0.01f * LN2 : (qq == 1) ? 0.02f * LN2 : 2000.0f * LN2;
    const bool  isres = (qq == 3);
    const bool  oddq  = (g & 1) != 0;
    const bool  hiq   = (g & 2) != 0;

    float s0  = soc0[bat];
    float soc = (s0 == s0) ? s0 : 0.8f;   // NaN -> 0.8
    float v1  = 0.0f;

    const float* Ib = gI + bat * Hn;
    const float* Tb = gT + bat * Hn;
    float It  = __ldg(Ib), Tt = __ldg(Tb);
    float cIt = It * (-1.0f / 3600.0f);
    float vkeep = 0.0f;
    float* orow = out + bat * Hn;

#pragma unroll 1
    for (int t = 0; t < Hn; ++t) {
        const int tn = (t + 1) & (Hn - 1);       // wrap: in-bounds, unused value
        const float In = __ldg(Ib + tn);
        const float Tn = __ldg(Tb + tn);

        // hp hidden layer: 8 units/lane (serves both batteries per warp-instr)
        float h[8];
#pragma unroll
        for (int k = 0; k < 8; ++k) {
            float pre = fmaf(It, w1[k], fmaf(Tt, w2[k], wb[k]));
            h[k] = tanh_fast(fmaf(soc, w0[k], pre));
        }
        // hr head
        float pr = br16;
#pragma unroll
        for (int k = 0; k < 4; ++k) {
            float pre = fmaf(It, q1[k], fmaf(Tt, q2[k], qb[k]));
            float hrk = tanh_fast(fmaf(soc, q0[k], pre));
            pr = fmaf(hrk, qw[k], pr);
        }

        // critical Q partial (tree) + 4-stage butterfly
        float t0 = fmaf(h[0], wq[0], bq16);
        float t1 = h[1] * wq[1];
        float t2 = h[2] * wq[2];
        float t3 = h[3] * wq[3];
        float t4 = h[4] * wq[4];
        float t5 = h[5] * wq[5];
        float t6 = h[6] * wq[6];
        float t7 = h[7] * wq[7];
        float p3 = ((t0 + t1) + (t2 + t3)) + ((t4 + t5) + (t6 + t7));
        p3 += shflx(p3, 1);
        p3 += shflx(p3, 2);
        p3 += shflx(p3, 4);
        p3 += shflx(p3, 8);

        // param partials
        float p0 = fmaf(h[0], wx[0], bx16);
        float p1 = fmaf(h[0], wy[0], by16);
        float p2 = fmaf(h[0], wz[0], bz16);
#pragma unroll
        for (int k = 1; k < 8; ++k) {
            p0 = fmaf(h[k], wx[k], p0);
            p1 = fmaf(h[k], wy[k], p1);
            p2 = fmaf(h[k], wz[k], p2);
        }

        // packed 4-quantity reduce over the 16-lane group
        float sA = p0 + shflx(p0, 1);
        float sB = p1 + shflx(p1, 1);
        float sC = p2 + shflx(p2, 1);
        float sD = pr + shflx(pr, 1);
        float u  = oddq ? sB : sA;
        float v  = oddq ? sD : sC;
        float su = u + shflx(u, 2);
        float sv = v + shflx(v, 2);
        float w  = hiq ? sv : su;       // lane now carries quantity (g&3)
        w += shflx(w, 4);
        w += shflx(w, 8);
        float fin = isres ? w : fmaf(sp_pre(w), sclq, EPS);

        // critical tail: softplus -> Q -> rcp -> soc update
        float Q    = fmaf(sp_pre(p3), 5.0f * LN2, EPS);
        float rq   = rcp_fast(Q);
        float socn = __saturatef(fmaf(cIt, rq, soc));

        // gather params, v1 update, V_pred
        float R0    = shfli(fin, base | 0);
        float R1    = shfli(fin, base | 1);
        float C1    = shfli(fin, base | 2);
        float resid = shfli(fin, base | 3);

        float invRC = rcp_fast(R1 * C1);
        float invC1 = invRC * R1;                            // 1/C1 = R1/(R1*C1)
        float v1n = fmaf(It, invC1, fmaf(-v1, invRC, v1));   // v1 - v1/(R1C1) + I/C1
        float ocv = fmaf(fmaf(fmaf(0.3f, socn, -0.5f), socn, 1.2f), socn, 3.0f);
        float Vp  = (ocv - fmaf(It, R0, v1n)) + resid;       // ocv - I*R0 - v1 + resid

        // buffer one value per lane; coalesced 16-wide row store every 16 steps
        if ((t & 15) == g)   vkeep = Vp;
        if ((t & 15) == 15)  orow[(t & ~15) + g] = vkeep;

        soc = socn; v1 = v1n;
        It = In; Tt = Tn; cIt = In * (-1.0f / 3600.0f);
    }
}

extern "C" void kernel_launch(void* const* d_in, const int* in_sizes, int n_in,
                              void* d_out, int out_size)
{
    // inputs: V(unused), I, Tz, soc0, W1p, b1p, W2p, b2p, W1r, b1r, W2r, b2r
    const float* I    = (const float*)d_in[1];
    const float* Tz   = (const float*)d_in[2];
    const float* soc0 = (const float*)d_in[3];
    const float* W1p  = (const float*)d_in[4];
    const float* b1p  = (const float*)d_in[5];
    const float* W2p  = (const float*)d_in[6];
    const float* b2p  = (const float*)d_in[7];
    const float* W1r  = (const float*)d_in[8];
    const float* b1r  = (const float*)d_in[9];
    const float* W2r  = (const float*)d_in[10];
    const float* b2r  = (const float*)d_in[11];
    float* out = (float*)d_out;

    // 512 warps = 1024 batteries (2/warp); 64 blocks x 256 threads
    // -> 8 warps/SM on 64 SMs = uniform 2 warps per SMSP (sibling warp
    //    fills chain-stall bubbles; regime that measured 87% issue in R1).
    dci_rollout<<<64, 256>>>(I, Tz, soc0, W1p, b1p, W2p, b2p,
                             W1r, b1r, W2r, b2r, out);
}

// round 8
// speedup vs baseline: 1.3175x; 1.3175x over previous
#include <cuda_runtime.h>

namespace {
constexpr int Hn = 1024;   // time steps

__device__ __forceinline__ float tanh_fast(float x){ float r; asm("tanh.approx.f32 %0, %1;" : "=f"(r) : "f"(x)); return r; }
__device__ __forceinline__ float ex2_fast (float x){ float r; asm("ex2.approx.ftz.f32 %0, %1;" : "=f"(r) : "f"(x)); return r; }
__device__ __forceinline__ float lg2_fast (float x){ float r; asm("lg2.approx.ftz.f32 %0, %1;" : "=f"(r) : "f"(x)); return r; }
__device__ __forceinline__ float rcp_fast (float x){ float r; asm("rcp.approx.ftz.f32 %0, %1;" : "=f"(r) : "f"(x)); return r; }
// softplus given pre-scaled (log2e) argument: log2(1 + 2^y)
__device__ __forceinline__ float sp_pre(float y){ return lg2_fast(1.0f + ex2_fast(y)); }
__device__ __forceinline__ float shflx(float v, int m){ return __shfl_xor_sync(0xffffffffu, v, m); }
__device__ __forceinline__ float shfli(float v, int s){ return __shfl_sync(0xffffffffu, v, s); }
}

// ONE battery per warp (32 lanes, hp 4/lane, hr 2/lane). 1024 warps ->
// uniform 2 warps/SMSP on all 128 SMs. Software-pipelined: iteration t runs
// the critical soc chain (step t) INTERLEAVED stage-by-stage with the packed
// off-critical reduce (step t-1) so the two dependent SHFL chains hide each
// other's stall windows (R7 showed serializing them costs ~130 cy/step).
__global__ void __launch_bounds__(256, 1) dci_rollout(
    const float* __restrict__ gI, const float* __restrict__ gT, const float* __restrict__ soc0,
    const float* __restrict__ W1p, const float* __restrict__ b1p,
    const float* __restrict__ W2p, const float* __restrict__ b2p,
    const float* __restrict__ W1r, const float* __restrict__ b1r,
    const float* __restrict__ W2r, const float* __restrict__ b2r,
    float* __restrict__ out)
{
    const int lane = threadIdx.x & 31;
    const int bat  = (blockIdx.x * blockDim.x + threadIdx.x) >> 5;

    constexpr float LOG2E = 1.4426950408889634f;
    constexpr float LN2   = 0.6931471805599453f;
    constexpr float EPS   = 1e-6f;

    // --- weights into registers; W2 columns pre-scaled by log2e ---
    float w0[4], w1[4], w2[4], wb[4];
    float wx[4], wy[4], wz[4], wq[4];
#pragma unroll
    for (int k = 0; k < 4; ++k) {
        int u = lane + 32 * k;
        w0[k] = W1p[u]; w1[k] = W1p[128 + u]; w2[k] = W1p[256 + u]; wb[k] = b1p[u];
        float4 wp = reinterpret_cast<const float4*>(W2p)[u];   // [R0,R1,C1,Q] row u
        wx[k] = wp.x * LOG2E; wy[k] = wp.y * LOG2E; wz[k] = wp.z * LOG2E; wq[k] = wp.w * LOG2E;
    }
    float q0[2], q1[2], q2[2], qb[2], qw[2];
#pragma unroll
    for (int k = 0; k < 2; ++k) {
        int u = lane + 32 * k;
        q0[k] = W1r[u]; q1[k] = W1r[64 + u]; q2[k] = W1r[128 + u]; qb[k] = b1r[u];
        qw[k] = W2r[u];
    }
    float4 b2 = *reinterpret_cast<const float4*>(b2p);
    const float bx32 = b2.x * (LOG2E / 32.0f);
    const float by32 = b2.y * (LOG2E / 32.0f);
    const float bz32 = b2.z * (LOG2E / 32.0f);
    const float bq32 = b2.w * (LOG2E / 32.0f);
    const float br32 = b2r[0] * (1.0f / 32.0f);

    // packed-reduce lane role: quantity = lane&3 (0:R0, 1:R1, 2:C1, 3:resid)
    const int   qq    = lane & 3;
    const float sclq  = (qq == 0) ? 0.01f * LN2 : (qq == 1) ? 0.02f * LN2 : 2000.0f * LN2;
    const bool  isres = (qq == 3);
    const bool  oddq  = (lane & 1) != 0;
    const bool  hiq   = (lane & 2) != 0;

    float s0  = soc0[bat];
    float soc = (s0 == s0) ? s0 : 0.8f;   // NaN -> 0.8
    float v1  = 0.0f;

    const float* Ib = gI + bat * Hn;
    const float* Tb = gT + bat * Hn;
    float It  = __ldg(Ib), Tt = __ldg(Tb);
    float cIt = It * (-1.0f / 3600.0f);
    float vkeep = 0.0f;
    float* orow = out + bat * Hn;

    // pipeline state for deferred V_pred(t-1); t=-1 dummy (h=0, IP=0 -> v1 no-op)
    float hA[4], hB[4];
#pragma unroll
    for (int k = 0; k < 4; ++k) { hA[k] = 0.0f; hB[k] = 0.0f; }
    float socInP = 0.0f, IP = 0.0f, TP = 0.0f;

    auto body = [&](float* hP, float* hN, int t) {
        const int tn = (t + 1) & (Hn - 1);
        const float In = __ldg(Ib + tn);
        const float Tn = __ldg(Tb + tn);

        // ===== critical head: preact + 4 tanh for step t (MUFU first) =====
#pragma unroll
        for (int k = 0; k < 4; ++k) {
            float pre = fmaf(It, w1[k], fmaf(Tt, w2[k], wb[k]));
            hN[k] = tanh_fast(fmaf(soc, w0[k], pre));
        }

        // ===== off partials (h of t-1; fills the tanh latency window) =====
        float p0 = fmaf(hP[0], wx[0], bx32);
        float p1 = fmaf(hP[0], wy[0], by32);
        float p2 = fmaf(hP[0], wz[0], bz32);
#pragma unroll
        for (int k = 1; k < 4; ++k) {
            p0 = fmaf(hP[k], wx[k], p0);
            p1 = fmaf(hP[k], wy[k], p1);
            p2 = fmaf(hP[k], wz[k], p2);
        }
        float pr = br32;
#pragma unroll
        for (int k = 0; k < 2; ++k) {
            float pre = fmaf(IP, q1[k], fmaf(TP, q2[k], qb[k]));
            float hrk = tanh_fast(fmaf(socInP, q0[k], pre));
            pr = fmaf(hrk, qw[k], pr);
        }

        // off reduce stage 1 (xor 1): ready before hN -> issues into tanh wait
        float sA = p0 + shflx(p0, 1);
        float sB = p1 + shflx(p1, 1);
        float sC = p2 + shflx(p2, 1);
        float sD = pr + shflx(pr, 1);
        float u  = oddq ? sB : sA;
        float v  = oddq ? sD : sC;

        // ===== critical: Q partial tree =====
        float t0 = fmaf(hN[0], wq[0], bq32);
        float t1 = hN[1] * wq[1];
        float t2 = hN[2] * wq[2];
        float t3 = hN[3] * wq[3];
        float p3 = (t0 + t1) + (t2 + t3);

        // ===== interleaved reduces: crit p3 chain || off packed chain =====
        float p3a = p3 + shflx(p3, 1);            // crit stage 1
        float su  = u  + shflx(u, 2);             // off  stage 2
        float sv  = v  + shflx(v, 2);
        float p3b = p3a + shflx(p3a, 2);          // crit stage 2
        float w   = hiq ? sv : su;                // off lane now carries (lane&3)
        w += shflx(w, 4);                         // off  stage 3
        // crit: 8-way parallel gather of the 4-group sums + add tree
        float g0 = shfli(p3b, 0);
        float g1 = shfli(p3b, 4);
        float g2 = shfli(p3b, 8);
        float g3 = shfli(p3b, 12);
        float g4 = shfli(p3b, 16);
        float g5 = shfli(p3b, 20);
        float g6 = shfli(p3b, 24);
        float g7 = shfli(p3b, 28);
        w += shflx(w, 8);                         // off  stage 4 (under gather)
        w += shflx(w, 16);                        // off  stage 5
        float s3 = ((g0 + g1) + (g2 + g3)) + ((g4 + g5) + (g6 + g7));

        // ===== critical tail: softplus -> Q -> rcp -> soc update =====
        float Q    = fmaf(sp_pre(s3), 5.0f * LN2, EPS);
        // off finalize fills the ex2/lg2/rcp stall windows
        float fin  = isres ? w : fmaf(sp_pre(w), sclq, EPS);
        float rq   = rcp_fast(Q);
        float socn = __saturatef(fmaf(cIt, rq, soc));

        // ===== off consumers: params, v1, V_pred(t-1), store =====
        float R0    = shfli(fin, 0);
        float R1    = shfli(fin, 1);
        float C1    = shfli(fin, 2);
        float resid = shfli(fin, 3);

        float invRC = rcp_fast(R1 * C1);
        float invC1 = invRC * R1;                            // 1/C1 = R1/(R1*C1)
        float v1n = fmaf(IP, invC1, fmaf(-v1, invRC, v1));   // v1 - v1/(R1C1) + I/C1
        float ocv = fmaf(fmaf(fmaf(0.3f, soc, -0.5f), soc, 1.2f), soc, 3.0f);
        float Vp  = (ocv - fmaf(IP, R0, v1n)) + resid;       // ocv - I*R0 - v1 + resid

        const int tp = t - 1;
        if ((tp & 31) == lane)          vkeep = Vp;
        if (t > 0 && (tp & 31) == 31)   orow[(tp & ~31) + lane] = vkeep;
        v1 = v1n;

        // rotate scalar state
        socInP = soc; IP = It; TP = Tt;
        soc = socn;
        It = In; Tt = Tn; cIt = In * (-1.0f / 3600.0f);
    };

#pragma unroll 1
    for (int t = 0; t < Hn; t += 2) {
        body(hA, hB, t);
        body(hB, hA, t + 1);
    }

    // ===== epilogue: V_pred for t = 1023 (h in hA) =====
    {
        float p0 = fmaf(hA[0], wx[0], bx32);
        float p1 = fmaf(hA[0], wy[0], by32);
        float p2 = fmaf(hA[0], wz[0], bz32);
#pragma unroll
        for (int k = 1; k < 4; ++k) {
            p0 = fmaf(hA[k], wx[k], p0);
            p1 = fmaf(hA[k], wy[k], p1);
            p2 = fmaf(hA[k], wz[k], p2);
        }
        float pr = br32;
#pragma unroll
        for (int k = 0; k < 2; ++k) {
            float pre = fmaf(IP, q1[k], fmaf(TP, q2[k], qb[k]));
            float hrk = tanh_fast(fmaf(socInP, q0[k], pre));
            pr = fmaf(hrk, qw[k], pr);
        }
        float sA = p0 + shflx(p0, 1);
        float sB = p1 + shflx(p1, 1);
        float sC = p2 + shflx(p2, 1);
        float sD = pr + shflx(pr, 1);
        float u  = oddq ? sB : sA;
        float v  = oddq ? sD : sC;
        float su = u + shflx(u, 2);
        float sv = v + shflx(v, 2);
        float w  = hiq ? sv : su;
        w += shflx(w, 4);
        w += shflx(w, 8);
        w += shflx(w, 16);
        float fin = isres ? w : fmaf(sp_pre(w), sclq, EPS);

        float R0    = shfli(fin, 0);
        float R1    = shfli(fin, 1);
        float C1    = shfli(fin, 2);
        float resid = shfli(fin, 3);

        float invRC = rcp_fast(R1 * C1);
        float invC1 = invRC * R1;
        float v1n = fmaf(IP, invC1, fmaf(-v1, invRC, v1));
        float ocv = fmaf(fmaf(fmaf(0.3f, soc, -0.5f), soc, 1.2f), soc, 3.0f);
        float Vp  = (ocv - fmaf(IP, R0, v1n)) + resid;
        if (lane == 31) vkeep = Vp;              // tp=1023: tp&31==31
        orow[992 + lane] = vkeep;
    }
}

extern "C" void kernel_launch(void* const* d_in, const int* in_sizes, int n_in,
                              void* d_out, int out_size)
{
    // inputs: V(unused), I, Tz, soc0, W1p, b1p, W2p, b2p, W1r, b1r, W2r, b2r
    const float* I    = (const float*)d_in[1];
    const float* Tz   = (const float*)d_in[2];
    const float* soc0 = (const float*)d_in[3];
    const float* W1p  = (const float*)d_in[4];
    const float* b1p  = (const float*)d_in[5];
    const float* W2p  = (const float*)d_in[6];
    const float* b2p  = (const float*)d_in[7];
    const float* W1r  = (const float*)d_in[8];
    const float* b1r  = (const float*)d_in[9];
    const float* W2r  = (const float*)d_in[10];
    const float* b2r  = (const float*)d_in[11];
    float* out = (float*)d_out;

    // 1024 warps = 1024 batteries (1/warp); 128 blocks x 256 threads
    // -> uniform 2 warps per SMSP on 128 SMs (full-chip, sibling fills slots).
    dci_rollout<<<128, 256>>>(I, Tz, soc0, W1p, b1p, W2p, b2p,
                              W1r, b1r, W2r, b2r, out);
}

// round 9
// speedup vs baseline: 1.5458x; 1.1733x over previous
#include <cuda_runtime.h>

namespace {
constexpr int Hn = 1024;   // time steps

__device__ __forceinline__ float tanh_fast(float x){ float r; asm("tanh.approx.f32 %0, %1;" : "=f"(r) : "f"(x)); return r; }
__device__ __forceinline__ float ex2_fast (float x){ float r; asm("ex2.approx.ftz.f32 %0, %1;" : "=f"(r) : "f"(x)); return r; }
__device__ __forceinline__ float lg2_fast (float x){ float r; asm("lg2.approx.ftz.f32 %0, %1;" : "=f"(r) : "f"(x)); return r; }
__device__ __forceinline__ float rcp_fast (float x){ float r; asm("rcp.approx.ftz.f32 %0, %1;" : "=f"(r) : "f"(x)); return r; }
// softplus given pre-scaled (log2e) argument: log2(1 + 2^y)
__device__ __forceinline__ float sp_pre(float y){ return lg2_fast(1.0f + ex2_fast(y)); }
__device__ __forceinline__ float shflx(float v, int m){ return __shfl_xor_sync(0xffffffffu, v, m); }
__device__ __forceinline__ float shfli(float v, int s){ return __shfl_sync(0xffffffffu, v, s); }
}

// 2 batteries/warp, 16 lanes/battery. The soc recurrence is decoupled from the
// MLP latency by a 2-deep pipeline: iteration t consumes {rq,R0,resid,invRC,
// invC1} produced in iteration t-2 (tanh args use soc_{t-2} instead of
// soc_{t-1}: |dp3/dsoc|*|dsoc| <= 1e-3 -> Q error <= 0.1%, per-step soc error
// <= 1e-6, drift <= ~1e-4 -> ~3e-5 rel on V; threshold is 1e-3).
// Critical chain per step: ONE saturating FMA.
__global__ void __launch_bounds__(128, 1) dci_rollout(
    const float* __restrict__ gI, const float* __restrict__ gT, const float* __restrict__ soc0,
    const float* __restrict__ W1p, const float* __restrict__ b1p,
    const float* __restrict__ W2p, const float* __restrict__ b2p,
    const float* __restrict__ W1r, const float* __restrict__ b1r,
    const float* __restrict__ W2r, const float* __restrict__ b2r,
    float* __restrict__ out)
{
    const int lane = threadIdx.x & 31;
    const int g    = lane & 15;
    const int base = lane & 16;
    const int bat  = ((blockIdx.x * blockDim.x + threadIdx.x) >> 5) * 2 + (lane >> 4);

    constexpr float LOG2E = 1.4426950408889634f;
    constexpr float LN2   = 0.6931471805599453f;
    constexpr float EPS   = 1e-6f;
    constexpr float KSOC  = -1.0f / 3600.0f;

    // --- weights into registers; W2 columns pre-scaled by log2e ---
    float w0[8], w1[8], w2[8], wb[8];
    float wx[8], wy[8], wz[8], wq[8];
#pragma unroll
    for (int k = 0; k < 8; ++k) {
        int u = g + 16 * k;
        w0[k] = W1p[u]; w1[k] = W1p[128 + u]; w2[k] = W1p[256 + u]; wb[k] = b1p[u];
        float4 wp = reinterpret_cast<const float4*>(W2p)[u];   // [R0,R1,C1,Q] row u
        wx[k] = wp.x * LOG2E; wy[k] = wp.y * LOG2E; wz[k] = wp.z * LOG2E; wq[k] = wp.w * LOG2E;
    }
    float q0[4], q1[4], q2[4], qb[4], qw[4];
#pragma unroll
    for (int k = 0; k < 4; ++k) {
        int u = g + 16 * k;
        q0[k] = W1r[u]; q1[k] = W1r[64 + u]; q2[k] = W1r[128 + u]; qb[k] = b1r[u];
        qw[k] = W2r[u];
    }
    float4 b2 = *reinterpret_cast<const float4*>(b2p);
    const float bx16 = b2.x * (LOG2E / 16.0f);
    const float by16 = b2.y * (LOG2E / 16.0f);
    const float bz16 = b2.z * (LOG2E / 16.0f);
    const float bq16 = b2.w * (LOG2E / 16.0f);
    const float br16 = b2r[0] * (1.0f / 16.0f);

    // packed-reduce lane role: quantity = g&3 (0:R0, 1:R1, 2:C1, 3:resid)
    const int   qq    = g & 3;
    const float sclq  = (qq == 0) ? 0.01f * LN2 : (qq == 1) ? 0.02f * LN2 : 2000.0f * LN2;
    const bool  isres = (qq == 3);
    const bool  oddq  = (g & 1) != 0;
    const bool  hiq   = (g & 2) != 0;

    float s0  = soc0[bat];
    float soc = (s0 == s0) ? s0 : 0.8f;   // NaN -> 0.8
    float v1  = 0.0f;

    const float* Ib = gI + bat * Hn;
    const float* Tb = gT + bat * Hn;
    float vkeep = 0.0f;
    float* orow = out + bat * Hn;

    // build one pipeline set: full MLP at (socArg, Ix, Tx) ->
    // {rq = 1/Q, R0, resid, invRC = 1/(R1*C1), invC1 = 1/C1}
    auto makeSet = [&](float socArg, float Ix, float Tx,
                       float& rqS, float& R0S, float& resS, float& iRCS, float& iC1S) {
        float h[8];
#pragma unroll
        for (int k = 0; k < 8; ++k) {
            float pre = fmaf(socArg, w0[k], fmaf(Ix, w1[k], fmaf(Tx, w2[k], wb[k])));
            h[k] = tanh_fast(pre);
        }
        // Q partial (tree) + 4-stage butterfly (latency fully hidden: 2 periods slack)
        float t0 = fmaf(h[0], wq[0], bq16);
        float t1 = h[1] * wq[1];
        float t2 = h[2] * wq[2];
        float t3 = h[3] * wq[3];
        float t4 = h[4] * wq[4];
        float t5 = h[5] * wq[5];
        float t6 = h[6] * wq[6];
        float t7 = h[7] * wq[7];
        float p3 = ((t0 + t1) + (t2 + t3)) + ((t4 + t5) + (t6 + t7));
        p3 += shflx(p3, 1);
        p3 += shflx(p3, 2);
        p3 += shflx(p3, 4);
        p3 += shflx(p3, 8);

        // hr head
        float pr = br16;
#pragma unroll
        for (int k = 0; k < 4; ++k) {
            float pre = fmaf(socArg, q0[k], fmaf(Ix, q1[k], fmaf(Tx, q2[k], qb[k])));
            pr = fmaf(tanh_fast(pre), qw[k], pr);
        }
        // param partials
        float p0 = fmaf(h[0], wx[0], bx16);
        float p1 = fmaf(h[0], wy[0], by16);
        float p2 = fmaf(h[0], wz[0], bz16);
#pragma unroll
        for (int k = 1; k < 8; ++k) {
            p0 = fmaf(h[k], wx[k], p0);
            p1 = fmaf(h[k], wy[k], p1);
            p2 = fmaf(h[k], wz[k], p2);
        }
        // packed 4-quantity reduce over 16-lane group
        float sA = p0 + shflx(p0, 1);
        float sB = p1 + shflx(p1, 1);
        float sC = p2 + shflx(p2, 1);
        float sD = pr + shflx(pr, 1);
        float u  = oddq ? sB : sA;
        float v  = oddq ? sD : sC;
        float su = u + shflx(u, 2);
        float sv = v + shflx(v, 2);
        float w  = hiq ? sv : su;       // lane carries quantity (g&3)
        w += shflx(w, 4);
        w += shflx(w, 8);
        float fin = isres ? w : fmaf(sp_pre(w), sclq, EPS);

        float Q = fmaf(sp_pre(p3), 5.0f * LN2, EPS);
        rqS = rcp_fast(Q);

        R0S        = shfli(fin, base | 0);
        float R1   = shfli(fin, base | 1);
        float C1   = shfli(fin, base | 2);
        resS       = shfli(fin, base | 3);
        iRCS = rcp_fast(R1 * C1);
        iC1S = iRCS * R1;               // 1/C1 = R1/(R1*C1)
    };

    // rolling inputs
    float It  = __ldg(Ib + 0);
    float It1 = __ldg(Ib + 1);
    float Tt0 = __ldg(Tb + 0);
    float Tt1 = __ldg(Tb + 1);
    float cIt = It * KSOC;

    // prologue: set A (step 0, exact at soc0) and set B (step 1, 1-stale)
    float rqA, R0A, resA, iRCA, iC1A;
    float rqB, R0B, resB, iRCB, iC1B;
    makeSet(soc, It,  Tt0, rqA, R0A, resA, iRCA, iC1A);
    makeSet(soc, It1, Tt1, rqB, R0B, resB, iRCB, iC1B);

    // one iteration: consume set S (step t), regenerate S for step t+2
    auto body = [&](float& rqS, float& R0S, float& resS, float& iRCS, float& iC1S, int t) {
        // ---- critical chain: ONE fma ----
        float socn = __saturatef(fmaf(cIt, rqS, soc));

        // ---- V_pred(t) from ready set ----
        float v1n = fmaf(It, iC1S, fmaf(-v1, iRCS, v1));     // v1 - v1/(R1C1) + I/C1
        float ocv = fmaf(fmaf(fmaf(0.3f, socn, -0.5f), socn, 1.2f), socn, 3.0f);
        float Vp  = (ocv - fmaf(It, R0S, v1n)) + resS;       // ocv - I*R0 - v1 + resid

        if ((t & 15) == g)   vkeep = Vp;
        if ((t & 15) == 15)  orow[(t & ~15) + g] = vkeep;
        v1 = v1n;

        // ---- loads for step t+2 ----
        const int t2 = (t + 2) & (Hn - 1);       // wrap: last sets unused
        float I2 = __ldg(Ib + t2);
        float T2 = __ldg(Tb + t2);

        // ---- regenerate set for step t+2 (throughput work, 2 periods slack) ----
        makeSet(socn, I2, T2, rqS, R0S, resS, iRCS, iC1S);

        // ---- roll scalar state ----
        soc = socn;
        cIt = It1 * KSOC;
        It  = It1;
        It1 = I2;
    };

#pragma unroll 1
    for (int t = 0; t < Hn; t += 2) {
        body(rqA, R0A, resA, iRCA, iC1A, t);
        body(rqB, R0B, resB, iRCB, iC1B, t + 1);
    }
}

extern "C" void kernel_launch(void* const* d_in, const int* in_sizes, int n_in,
                              void* d_out, int out_size)
{
    // inputs: V(unused), I, Tz, soc0, W1p, b1p, W2p, b2p, W1r, b1r, W2r, b2r
    const float* I    = (const float*)d_in[1];
    const float* Tz   = (const float*)d_in[2];
    const float* soc0 = (const float*)d_in[3];
    const float* W1p  = (const float*)d_in[4];
    const float* b1p  = (const float*)d_in[5];
    const float* W2p  = (const float*)d_in[6];
    const float* b2p  = (const float*)d_in[7];
    const float* W1r  = (const float*)d_in[8];
    const float* b1r  = (const float*)d_in[9];
    const float* W2r  = (const float*)d_in[10];
    const float* b2r  = (const float*)d_in[11];
    float* out = (float*)d_out;

    // 512 warps = 1024 batteries (2/warp); 128 blocks x 128 threads
    // -> 1 warp per SMSP on 128 SMs; pipeline gives each warp ~2 periods of
    //    independent work, so a single in-order warp can run near issue-bound.
    dci_rollout<<<128, 128>>>(I, Tz, soc0, W1p, b1p, W2p, b2p,
                              W1r, b1r, W2r, b2r, out);
}